// round 6
// baseline (speedup 1.0000x reference)
#include <cuda_runtime.h>

#define FULLMASK 0xffffffffu

constexpr int Bb = 4;
constexpr int N1 = 8192, S1 = 2048, K1 = 32, C1 = 128;
constexpr int N2 = 2048, S2 = 256,  K2 = 16, C2 = 693;
constexpr int SMAX = 693;

// ------------- static device scratch (no runtime allocation allowed) -------------
__device__ float4 g_pack1[Bb * N1];     // (x,y,z,||p||^2) level-1 coords
__device__ float4 g_cent1[Bb * S1];     // l1 centers (= l1_xyz), with norms
__device__ float4 g_cent2[Bb * S2];     // l2 centers
__device__ int    g_fps1[Bb * S1];
__device__ int    g_fps2[Bb * S2];
__device__ int    g_ball1[Bb * S1 * K1];
__device__ int    g_ball2[Bb * S2 * K2];
__device__ float  g_h1[(size_t)Bb * S1 * K1 * C1];   // ~134 MB
__device__ float  g_h2[(size_t)Bb * S2 * K2 * C2];   // ~45 MB
__device__ float  g_l1pts[(size_t)Bb * S1 * C1];
__device__ double g_sums[2 * SMAX];
__device__ float  g_mu[SMAX];
__device__ float  g_rs[SMAX];

// (x^2 + y^2) + z^2 with explicit rounding (no FMA contraction) — matches
// XLA's elementwise mul + sequential axis(-1) reduce.
__device__ __forceinline__ float sq3(float x, float y, float z) {
    return __fadd_rn(__fadd_rn(__fmul_rn(x, x), __fmul_rn(y, y)), __fmul_rn(z, z));
}

// ---------------- pack coords + squared norm ----------------
__global__ void k_pack1(const float* __restrict__ xyz, float4* __restrict__ pack) {
    int i = blockIdx.x * blockDim.x + threadIdx.x;
    if (i >= Bb * N1) return;
    float x = xyz[(size_t)i * 6 + 0];
    float y = xyz[(size_t)i * 6 + 1];
    float z = xyz[(size_t)i * 6 + 2];
    pack[i] = make_float4(x, y, z, sq3(x, y, z));
}

// ---------------- farthest point sampling: one block per batch ----------------
// Records farthest BEFORE updating (scan emits the carry), first index = 0.
// Argmax semantics: max value, ties -> lowest index (jnp.argmax / XLA).
template <int N, int S, int T, int PPT>
__global__ void __launch_bounds__(T) k_fps(const float4* __restrict__ pack,
                                           int* __restrict__ outIdx) {
    int b = blockIdx.x, t = threadIdx.x;
    const float4* p = pack + (size_t)b * N;
    float px[PPT], py[PPT], pz[PPT], dd[PPT];
#pragma unroll
    for (int j = 0; j < PPT; j++) {
        float4 v = p[t + j * T];
        px[j] = v.x; py[j] = v.y; pz[j] = v.z; dd[j] = 1e10f;
    }
    __shared__ float scx, scy, scz;
    __shared__ int sfar;
    __shared__ unsigned swv[32];
    __shared__ int swi[32];
    int* oi = outIdx + b * S;
    int f = 0;
    int lane = t & 31, wid = t >> 5;
    for (int it = 0; it < S; ++it) {
        // owner of point f publishes its coords (unique (t,j) matches)
#pragma unroll
        for (int j = 0; j < PPT; j++)
            if (f == t + j * T) { scx = px[j]; scy = py[j]; scz = pz[j]; }
        if (t == 0) oi[it] = f;
        __syncthreads();
        float cx = scx, cy = scy, cz = scz;
        unsigned ub = 0u; int bi = 0x7fffffff;
#pragma unroll
        for (int j = 0; j < PPT; j++) {
            float dx = __fsub_rn(px[j], cx);
            float dy = __fsub_rn(py[j], cy);
            float dz = __fsub_rn(pz[j], cz);
            float d  = sq3(dx, dy, dz);
            float nd = fminf(dd[j], d);
            dd[j] = nd;
            unsigned nb = __float_as_uint(nd);   // nd >= 0 -> bits are order-preserving
            int gi = t + j * T;
            if (nb > ub || (nb == ub && gi < bi)) { ub = nb; bi = gi; }
        }
        unsigned mv = __reduce_max_sync(FULLMASK, ub);
        int mi = __reduce_min_sync(FULLMASK, (ub == mv) ? bi : 0x7fffffff);
        if (lane == 0) { swv[wid] = mv; swi[wid] = mi; }
        __syncthreads();
        if (t < 32) {
            constexpr int NW = T / 32;
            unsigned u2 = (t < NW) ? swv[t] : 0u;
            int i2 = (t < NW) ? swi[t] : 0x7fffffff;
            unsigned m2 = __reduce_max_sync(FULLMASK, u2);
            int r2i = __reduce_min_sync(FULLMASK, (u2 == m2) ? i2 : 0x7fffffff);
            if (t == 0) sfar = r2i;
        }
        __syncthreads();
        f = sfar;
    }
}

// ---------------- gather sampled centers (and optionally emit l2_xyz) ----------------
__global__ void k_gather(const float4* __restrict__ pack, const int* __restrict__ fps,
                         float4* __restrict__ cent, int S, int N,
                         float* __restrict__ xyzOut) {
    int i = blockIdx.x * blockDim.x + threadIdx.x;
    if (i >= Bb * S) return;
    int b = i / S;
    float4 v = pack[b * N + fps[i]];
    cent[i] = v;
    if (xyzOut) {
        xyzOut[(size_t)i * 3 + 0] = v.x;
        xyzOut[(size_t)i * 3 + 1] = v.y;
        xyzOut[(size_t)i * 3 + 2] = v.z;
    }
}

// ---------------- ball query: one warp per center ----------------
// sqrdist = (||s||^2 + ||p||^2) - 2*dot  (reference's cancellation formula).
// Keep if !(sqrdist > r2). First K ascending indices; pad with first hit;
// if no hit, all indices = N (JAX gather clamps to N-1).
template <int NPTS, int K>
__global__ void k_ball(const float4* __restrict__ pack, const float4* __restrict__ cent,
                       int S, float r2, int* __restrict__ out) {
    int lane = threadIdx.x & 31;
    int cid = (blockIdx.x * blockDim.x + threadIdx.x) >> 5;
    if (cid >= Bb * S) return;
    int b = cid / S;
    float4 c = cent[cid];
    const float4* p = pack + (size_t)b * NPTS;
    int* o = out + (size_t)cid * K;
    int cnt = 0, first = -1;
    for (int base = 0; base < NPTS && cnt < K; base += 32) {
        float4 q = p[base + lane];
        float dot = fmaf(c.z, q.z, fmaf(c.y, q.y, __fmul_rn(c.x, q.x)));
        float sq = __fsub_rn(__fadd_rn(c.w, q.w), __fmul_rn(2.0f, dot));
        bool in = !(sq > r2);
        unsigned bm = __ballot_sync(FULLMASK, in);
        int pos = cnt + __popc(bm & ((1u << lane) - 1u));
        if (in && pos < K) o[pos] = base + lane;
        if (first < 0 && bm) first = base + __ffs(bm) - 1;
        cnt += __popc(bm);
    }
    if (first < 0) first = NPTS - 1;   // empty ball: idx n, clamped at gather
    for (int pos = min(cnt, K) + lane; pos < K; pos += 32) o[pos] = first;
}

// ---------------- zero the BN accumulators ----------------
__global__ void k_zero() {
    int i = blockIdx.x * blockDim.x + threadIdx.x;
    if (i < 2 * SMAX) g_sums[i] = 0.0;
}

// ---------------- level-1 MLP: h = [coords-diff | norm-feat] @ w1 + b1 ----------------
__global__ void k_mlp1(const float* __restrict__ xyz,
                       const float* __restrict__ w1, const float* __restrict__ b1) {
    __shared__ float F[K1 * 6];
    int bs = blockIdx.x, t = threadIdx.x;
    int b = bs / S1;
    if (t < K1) {
        int idx = g_ball1[bs * K1 + t];
        float4 p = g_pack1[b * N1 + idx];
        float4 c = g_cent1[bs];
        const float* nr = xyz + (size_t)(b * N1 + idx) * 6 + 3;
        F[t * 6 + 0] = __fsub_rn(p.x, c.x);
        F[t * 6 + 1] = __fsub_rn(p.y, c.y);
        F[t * 6 + 2] = __fsub_rn(p.z, c.z);
        F[t * 6 + 3] = nr[0];
        F[t * 6 + 4] = nr[1];
        F[t * 6 + 5] = nr[2];
    }
    __syncthreads();
    float w[6];
#pragma unroll
    for (int j = 0; j < 6; j++) w[j] = w1[j * C1 + t];
    float bias = b1[t];
    double ds = 0.0, dq = 0.0;
    float* op = g_h1 + (size_t)bs * K1 * C1 + t;
#pragma unroll 4
    for (int k = 0; k < K1; k++) {
        const float* fv = F + k * 6;
        float h = fmaf(fv[0], w[0], 0.0f);
#pragma unroll
        for (int j = 1; j < 6; j++) h = fmaf(fv[j], w[j], h);
        h = __fadd_rn(h, bias);
        op[(size_t)k * C1] = h;
        ds += (double)h;
        dq += (double)h * (double)h;
    }
    atomicAdd(&g_sums[t], ds);
    atomicAdd(&g_sums[SMAX + t], dq);
}

// ---------------- BN statistics: mu, rsqrt(var + eps) ----------------
__global__ void k_stats(int C, double M) {
    int t = blockIdx.x * blockDim.x + threadIdx.x;
    if (t >= C) return;
    double m = g_sums[t] / M;
    double var = g_sums[SMAX + t] / M - m * m;
    float vf = (float)var;
    g_mu[t] = (float)m;
    g_rs[t] = (float)(1.0 / sqrt((double)__fadd_rn(vf, 1e-5f)));
}

// ---------------- level-1 normalize + relu + max over k ----------------
__global__ void k_nm1(const float* __restrict__ g1, const float* __restrict__ be1) {
    int bs = blockIdx.x, c = threadIdx.x;
    float mu = g_mu[c], rs = g_rs[c], ga = g1[c], be = be1[c];
    const float* hp = g_h1 + (size_t)bs * K1 * C1 + c;
    float m = __int_as_float(0xff800000);   // -inf
#pragma unroll 4
    for (int k = 0; k < K1; k++) {
        float h = hp[(size_t)k * C1];
        float v = __fadd_rn(__fmul_rn(__fmul_rn(__fsub_rn(h, mu), rs), ga), be);
        m = fmaxf(m, fmaxf(v, 0.0f));
    }
    g_l1pts[(size_t)bs * C1 + c] = m;
}

// ---------------- level-2 MLP: 131-channel input (3 coord-diff + 128 l1 feats) ----------------
__global__ void k_mlp2(const float* __restrict__ w2, const float* __restrict__ b2) {
    __shared__ __align__(16) float FT[131 * 16];   // FT[j][k], k-contiguous
    int bs = blockIdx.x, t = threadIdx.x;
    int b = bs / S2;
    for (int e = t; e < 131 * 16; e += blockDim.x) {
        int k = e / 131, j = e - k * 131;
        int idx = g_ball2[bs * K2 + k];
        float v;
        if (j < 3) {
            float4 p = g_cent1[b * N2 + idx];
            float4 c = g_cent2[bs];
            v = (j == 0) ? __fsub_rn(p.x, c.x)
              : (j == 1) ? __fsub_rn(p.y, c.y)
                         : __fsub_rn(p.z, c.z);
        } else {
            v = g_l1pts[(size_t)(b * N2 + idx) * C1 + (j - 3)];
        }
        FT[j * 16 + k] = v;
    }
    __syncthreads();
    if (t >= C2) return;
    float acc[16];
#pragma unroll
    for (int k = 0; k < 16; k++) acc[k] = 0.0f;
    for (int j = 0; j < 131; j++) {
        float wj = w2[j * C2 + t];
        const float4* fp = (const float4*)(FT + j * 16);
#pragma unroll
        for (int q = 0; q < 4; q++) {
            float4 fv = fp[q];
            acc[q * 4 + 0] = fmaf(fv.x, wj, acc[q * 4 + 0]);
            acc[q * 4 + 1] = fmaf(fv.y, wj, acc[q * 4 + 1]);
            acc[q * 4 + 2] = fmaf(fv.z, wj, acc[q * 4 + 2]);
            acc[q * 4 + 3] = fmaf(fv.w, wj, acc[q * 4 + 3]);
        }
    }
    float bias = b2[t];
    double ds = 0.0, dq = 0.0;
    float* op = g_h2 + (size_t)bs * K2 * C2 + t;
#pragma unroll
    for (int k = 0; k < 16; k++) {
        float h = __fadd_rn(acc[k], bias);
        op[(size_t)k * C2] = h;
        ds += (double)h;
        dq += (double)h * (double)h;
    }
    atomicAdd(&g_sums[t], ds);
    atomicAdd(&g_sums[SMAX + t], dq);
}

// ---------------- level-2 normalize + relu + max over k -> l2_pts ----------------
__global__ void k_nm2(const float* __restrict__ g2, const float* __restrict__ be2,
                      float* __restrict__ out) {
    int bs = blockIdx.x, c = threadIdx.x;
    if (c >= C2) return;
    float mu = g_mu[c], rs = g_rs[c], ga = g2[c], be = be2[c];
    const float* hp = g_h2 + (size_t)bs * K2 * C2 + c;
    float m = __int_as_float(0xff800000);
#pragma unroll
    for (int k = 0; k < K2; k++) {
        float h = hp[(size_t)k * C2];
        float v = __fadd_rn(__fmul_rn(__fmul_rn(__fsub_rn(h, mu), rs), ga), be);
        m = fmaxf(m, fmaxf(v, 0.0f));
    }
    out[(size_t)bs * C2 + c] = m;
}

// ==================================================================================
extern "C" void kernel_launch(void* const* d_in, const int* in_sizes, int n_in,
                              void* d_out, int out_size) {
    const float* xyz = (const float*)d_in[0];
    const float* w1  = (const float*)d_in[1];
    const float* b1  = (const float*)d_in[2];
    const float* g1  = (const float*)d_in[3];
    const float* be1 = (const float*)d_in[4];
    const float* w2  = (const float*)d_in[5];
    const float* b2  = (const float*)d_in[6];
    const float* g2  = (const float*)d_in[7];
    const float* be2 = (const float*)d_in[8];
    float* out = (float*)d_out;
    float* l2xyz = out;                    // (4,256,3)
    float* l2pts = out + Bb * S2 * 3;      // (4,256,693)

    void *pP1, *pC1, *pC2, *pF1, *pF2, *pB1, *pB2;
    cudaGetSymbolAddress(&pP1, g_pack1);
    cudaGetSymbolAddress(&pC1, g_cent1);
    cudaGetSymbolAddress(&pC2, g_cent2);
    cudaGetSymbolAddress(&pF1, g_fps1);
    cudaGetSymbolAddress(&pF2, g_fps2);
    cudaGetSymbolAddress(&pB1, g_ball1);
    cudaGetSymbolAddress(&pB2, g_ball2);
    float4* P1 = (float4*)pP1;
    float4* Cn1 = (float4*)pC1;
    float4* Cn2 = (float4*)pC2;
    int* F1 = (int*)pF1;
    int* F2 = (int*)pF2;
    int* Ball1 = (int*)pB1;
    int* Ball2 = (int*)pB2;

    const float r2_1 = (float)(0.0025 * 0.0025);
    const float r2_2 = (float)(0.005 * 0.005);

    // ---- level 1 ----
    k_pack1<<<(Bb * N1 + 255) / 256, 256>>>(xyz, P1);
    k_fps<N1, S1, 1024, 8><<<Bb, 1024>>>(P1, F1);
    k_gather<<<(Bb * S1 + 255) / 256, 256>>>(P1, F1, Cn1, S1, N1, nullptr);
    k_ball<N1, K1><<<(Bb * S1) / 8, 256>>>(P1, Cn1, S1, r2_1, Ball1);
    k_zero<<<2, 704>>>();
    k_mlp1<<<Bb * S1, C1>>>(xyz, w1, b1);
    k_stats<<<1, 704>>>(C1, (double)(Bb * S1 * K1));
    k_nm1<<<Bb * S1, C1>>>(g1, be1);

    // ---- level 2 ----
    k_fps<N2, S2, 512, 4><<<Bb, 512>>>(Cn1, F2);
    k_gather<<<(Bb * S2 + 255) / 256, 256>>>(Cn1, F2, Cn2, S2, N2, l2xyz);
    k_ball<N2, K2><<<(Bb * S2) / 8, 256>>>(Cn1, Cn2, S2, r2_2, Ball2);
    k_zero<<<2, 704>>>();
    k_mlp2<<<Bb * S2, 704>>>(w2, b2);
    k_stats<<<1, 704>>>(C2, (double)(Bb * S2 * K2));
    k_nm2<<<Bb * S2, 704>>>(g2, be2, l2pts);
}

// round 7
// speedup vs baseline: 1.6718x; 1.6718x over previous
#include <cuda_runtime.h>

#define FULLMASK 0xffffffffu
typedef unsigned long long ull;

constexpr int Bb = 4;
constexpr int N1 = 8192, S1 = 2048, K1 = 32, C1 = 128;
constexpr int N2 = 2048, S2 = 256,  K2 = 16, C2 = 693;
constexpr int SMAX = 693;

// ------------- static device scratch (no runtime allocation allowed) -------------
__device__ float4 g_pack1[Bb * N1];     // (x,y,z,||p||^2) level-1 coords
__device__ float4 g_cent1[Bb * S1];     // l1 centers (= l1_xyz), with norms
__device__ float4 g_cent2[Bb * S2];     // l2 centers
__device__ int    g_fps1[Bb * S1];
__device__ int    g_fps2[Bb * S2];
__device__ int    g_ball1[Bb * S1 * K1];
__device__ int    g_ball2[Bb * S2 * K2];
__device__ float  g_h2[(size_t)Bb * S2 * K2 * C2];   // ~45 MB
__device__ float  g_l1pts[(size_t)Bb * S1 * C1];
__device__ double g_sums[2 * SMAX];
__device__ float  g_mu[SMAX];
__device__ float  g_rs[SMAX];

// ---------------- packed f32x2 helpers (each lane = IEEE rn op, identical to scalar) ----------------
__device__ __forceinline__ ull pk2(float a, float b) {
    ull r; asm("mov.b64 %0,{%1,%2};" : "=l"(r) : "f"(a), "f"(b)); return r;
}
__device__ __forceinline__ void upk2(ull v, float& a, float& b) {
    asm("mov.b64 {%0,%1},%2;" : "=f"(a), "=f"(b) : "l"(v));
}
__device__ __forceinline__ ull f2add(ull a, ull b) {
    ull r; asm("add.rn.f32x2 %0,%1,%2;" : "=l"(r) : "l"(a), "l"(b)); return r;
}
__device__ __forceinline__ ull f2mul(ull a, ull b) {
    ull r; asm("mul.rn.f32x2 %0,%1,%2;" : "=l"(r) : "l"(a), "l"(b)); return r;
}

// (x^2 + y^2) + z^2 with explicit rounding (no FMA contraction) — matches
// XLA's elementwise mul + sequential axis(-1) reduce.
__device__ __forceinline__ float sq3(float x, float y, float z) {
    return __fadd_rn(__fadd_rn(__fmul_rn(x, x), __fmul_rn(y, y)), __fmul_rn(z, z));
}

// ---------------- pack coords + squared norm ----------------
__global__ void k_pack1(const float* __restrict__ xyz, float4* __restrict__ pack) {
    int i = blockIdx.x * blockDim.x + threadIdx.x;
    if (i >= Bb * N1) return;
    float x = xyz[(size_t)i * 6 + 0];
    float y = xyz[(size_t)i * 6 + 1];
    float z = xyz[(size_t)i * 6 + 2];
    pack[i] = make_float4(x, y, z, sq3(x, y, z));
}

// ---------------- farthest point sampling v2: one block per batch ----------------
// 1 barrier/iter: per-warp reduce -> double-buffered shared -> every warp
// redundantly reduces the warp candidates (no second barrier, no broadcast step).
// Coordinates mirrored in shared memory so the centroid is a broadcast LDS.
// Distance math in packed f32x2; per-lane rounding identical to the scalar
// no-FMA form (a + (-b) == a - b exactly). Ties -> lowest index (jnp.argmax).
template <int N, int S, int T, int PPT>
__global__ void __launch_bounds__(T) k_fps(const float4* __restrict__ pack,
                                           int* __restrict__ outIdx) {
    extern __shared__ float sm[];
    float* sx = sm; float* sy = sm + N; float* sz = sm + 2 * N;
    __shared__ unsigned sv[2][32];
    __shared__ int si[2][32];
    constexpr int NP = PPT / 2;
    constexpr int NW = T / 32;
    int b = blockIdx.x, t = threadIdx.x;
    const float4* p = pack + (size_t)b * N;

    ull px2[NP], py2[NP], pz2[NP];
    float dd[PPT];
    {
        float pxs[PPT], pys[PPT], pzs[PPT];
#pragma unroll
        for (int j = 0; j < PPT; j++) {
            int i = t + j * T;
            float4 v = p[i];
            sx[i] = v.x; sy[i] = v.y; sz[i] = v.z;
            pxs[j] = v.x; pys[j] = v.y; pzs[j] = v.z;
            dd[j] = 1e10f;
        }
#pragma unroll
        for (int q = 0; q < NP; q++) {
            px2[q] = pk2(pxs[2 * q], pxs[2 * q + 1]);
            py2[q] = pk2(pys[2 * q], pys[2 * q + 1]);
            pz2[q] = pk2(pzs[2 * q], pzs[2 * q + 1]);
        }
    }
    __syncthreads();

    int* oi = outIdx + b * S;
    int lane = t & 31, wid = t >> 5;
    int f = 0;
    for (int it = 0; it < S; ++it) {
        if (t == 0) oi[it] = f;
        float cx = sx[f], cy = sy[f], cz = sz[f];     // broadcast LDS
        ull ncx = pk2(-cx, -cx), ncy = pk2(-cy, -cy), ncz = pk2(-cz, -cz);
        float m = __int_as_float(0xff800000);
#pragma unroll
        for (int q = 0; q < NP; q++) {
            ull dx = f2add(px2[q], ncx);
            ull dy = f2add(py2[q], ncy);
            ull dz = f2add(pz2[q], ncz);
            ull s = f2add(f2add(f2mul(dx, dx), f2mul(dy, dy)), f2mul(dz, dz));
            float lo, hi; upk2(s, lo, hi);
            float n0 = fminf(dd[2 * q], lo);
            float n1 = fminf(dd[2 * q + 1], hi);
            dd[2 * q] = n0; dd[2 * q + 1] = n1;
            m = fmaxf(m, fmaxf(n0, n1));
        }
        unsigned mb = __float_as_uint(m);             // dd >= 0 -> bits order-preserving
        unsigned wmax = __reduce_max_sync(FULLMASK, mb);
        int cand = 0x7fffffff;
        if (mb == wmax) {                             // ~1 warp in NW enters
#pragma unroll
            for (int j = PPT - 1; j >= 0; j--)
                if (__float_as_uint(dd[j]) == wmax) cand = t + j * T;
        }
        int wi = __reduce_min_sync(FULLMASK, cand);
        int par = it & 1;
        if (lane == 0) { sv[par][wid] = wmax; si[par][wid] = wi; }
        __syncthreads();
        unsigned u2 = (lane < NW) ? sv[par][lane] : 0u;
        int i2 = (lane < NW) ? si[par][lane] : 0x7fffffff;
        unsigned m2 = __reduce_max_sync(FULLMASK, u2);
        f = __reduce_min_sync(FULLMASK, (u2 == m2) ? i2 : 0x7fffffff);
    }
}

// ---------------- gather sampled centers (and optionally emit l2_xyz) ----------------
__global__ void k_gather(const float4* __restrict__ pack, const int* __restrict__ fps,
                         float4* __restrict__ cent, int S, int N,
                         float* __restrict__ xyzOut) {
    int i = blockIdx.x * blockDim.x + threadIdx.x;
    if (i >= Bb * S) return;
    int b = i / S;
    float4 v = pack[b * N + fps[i]];
    cent[i] = v;
    if (xyzOut) {
        xyzOut[(size_t)i * 3 + 0] = v.x;
        xyzOut[(size_t)i * 3 + 1] = v.y;
        xyzOut[(size_t)i * 3 + 2] = v.z;
    }
}

// ---------------- ball query: one warp per center, unroll-4 for MLP ----------------
// sqrdist = (||s||^2 + ||p||^2) - 2*dot  (reference's cancellation formula).
// Keep if !(sqrdist > r2). First K ascending indices; pad with first hit;
// if no hit, all indices = N (JAX gather clamps to N-1). Early-exit checked
// every 128 points so 4 LDG.128 stay in flight.
template <int NPTS, int K>
__global__ void k_ball(const float4* __restrict__ pack, const float4* __restrict__ cent,
                       int S, float r2, int* __restrict__ out) {
    int lane = threadIdx.x & 31;
    int cid = (blockIdx.x * blockDim.x + threadIdx.x) >> 5;
    if (cid >= Bb * S) return;
    int b = cid / S;
    float4 c = cent[cid];
    const float4* p = pack + (size_t)b * NPTS;
    int* o = out + (size_t)cid * K;
    int cnt = 0, first = -1;
    for (int base = 0; base < NPTS && cnt < K; base += 128) {
        float4 q[4];
#pragma unroll
        for (int u = 0; u < 4; u++) q[u] = p[base + u * 32 + lane];
#pragma unroll
        for (int u = 0; u < 4; u++) {
            float dot = fmaf(c.z, q[u].z, fmaf(c.y, q[u].y, __fmul_rn(c.x, q[u].x)));
            float sq = __fsub_rn(__fadd_rn(c.w, q[u].w), __fmul_rn(2.0f, dot));
            bool in = !(sq > r2);
            unsigned bm = __ballot_sync(FULLMASK, in);
            int pos = cnt + __popc(bm & ((1u << lane) - 1u));
            if (in && pos < K) o[pos] = base + u * 32 + lane;
            if (first < 0 && bm) first = base + u * 32 + __ffs(bm) - 1;
            cnt += __popc(bm);
        }
    }
    if (first < 0) first = NPTS - 1;   // empty ball: idx n, clamped at gather
    for (int pos = min(cnt, K) + lane; pos < K; pos += 32) o[pos] = first;
}

// ---------------- zero the BN accumulators ----------------
__global__ void k_zero() {
    int i = blockIdx.x * blockDim.x + threadIdx.x;
    if (i < 2 * SMAX) g_sums[i] = 0.0;
}

// ---------------- level-1 feature gather (shared by both passes) ----------------
__device__ __forceinline__ void l1_gather(float* F, const float* __restrict__ xyz,
                                          int bs, int b, int t) {
    if (t < K1) {
        int idx = g_ball1[bs * K1 + t];
        float4 p = g_pack1[b * N1 + idx];
        float4 c = g_cent1[bs];
        const float* nr = xyz + (size_t)(b * N1 + idx) * 6 + 3;
        F[t * 6 + 0] = __fsub_rn(p.x, c.x);
        F[t * 6 + 1] = __fsub_rn(p.y, c.y);
        F[t * 6 + 2] = __fsub_rn(p.z, c.z);
        F[t * 6 + 3] = nr[0];
        F[t * 6 + 4] = nr[1];
        F[t * 6 + 5] = nr[2];
    }
}

__device__ __forceinline__ float l1_h(const float* fv, const float* w, float bias) {
    float h = fmaf(fv[0], w[0], 0.0f);
#pragma unroll
    for (int j = 1; j < 6; j++) h = fmaf(fv[j], w[j], h);
    return __fadd_rn(h, bias);
}

// ---------------- level-1 MLP pass A: statistics only (h not materialized) ----------------
__global__ void k_mlp1(const float* __restrict__ xyz,
                       const float* __restrict__ w1, const float* __restrict__ b1) {
    __shared__ float F[K1 * 6];
    int bs = blockIdx.x, t = threadIdx.x;
    l1_gather(F, xyz, bs, bs / S1, t);
    __syncthreads();
    float w[6];
#pragma unroll
    for (int j = 0; j < 6; j++) w[j] = w1[j * C1 + t];
    float bias = b1[t];
    double ds = 0.0, dq = 0.0;
#pragma unroll 4
    for (int k = 0; k < K1; k++) {
        float h = l1_h(F + k * 6, w, bias);
        ds += (double)h;
        dq += (double)h * (double)h;
    }
    atomicAdd(&g_sums[t], ds);
    atomicAdd(&g_sums[SMAX + t], dq);
}

// ---------------- BN statistics: mu, rsqrt(var + eps) ----------------
__global__ void k_stats(int C, double M) {
    int t = blockIdx.x * blockDim.x + threadIdx.x;
    if (t >= C) return;
    double m = g_sums[t] / M;
    double var = g_sums[SMAX + t] / M - m * m;
    float vf = (float)var;
    g_mu[t] = (float)m;
    g_rs[t] = (float)(1.0 / sqrt((double)__fadd_rn(vf, 1e-5f)));
}

// ---------------- level-1 pass B: recompute h (bit-identical), normalize+relu+max ----------------
__global__ void k_nm1(const float* __restrict__ xyz,
                      const float* __restrict__ w1, const float* __restrict__ b1,
                      const float* __restrict__ g1, const float* __restrict__ be1) {
    __shared__ float F[K1 * 6];
    int bs = blockIdx.x, t = threadIdx.x;
    l1_gather(F, xyz, bs, bs / S1, t);
    __syncthreads();
    float w[6];
#pragma unroll
    for (int j = 0; j < 6; j++) w[j] = w1[j * C1 + t];
    float bias = b1[t];
    float mu = g_mu[t], rs = g_rs[t], ga = g1[t], be = be1[t];
    float m = __int_as_float(0xff800000);
#pragma unroll 4
    for (int k = 0; k < K1; k++) {
        float h = l1_h(F + k * 6, w, bias);
        float v = __fadd_rn(__fmul_rn(__fmul_rn(__fsub_rn(h, mu), rs), ga), be);
        m = fmaxf(m, fmaxf(v, 0.0f));
    }
    g_l1pts[(size_t)bs * C1 + t] = m;
}

// ---------------- level-2 MLP: 131-channel input (3 coord-diff + 128 l1 feats) ----------------
__global__ void k_mlp2(const float* __restrict__ w2, const float* __restrict__ b2) {
    __shared__ __align__(16) float FT[131 * 16];   // FT[j][k], k-contiguous
    int bs = blockIdx.x, t = threadIdx.x;
    int b = bs / S2;
    for (int e = t; e < 131 * 16; e += blockDim.x) {
        int k = e / 131, j = e - k * 131;
        int idx = g_ball2[bs * K2 + k];
        float v;
        if (j < 3) {
            float4 p = g_cent1[b * N2 + idx];
            float4 c = g_cent2[bs];
            v = (j == 0) ? __fsub_rn(p.x, c.x)
              : (j == 1) ? __fsub_rn(p.y, c.y)
                         : __fsub_rn(p.z, c.z);
        } else {
            v = g_l1pts[(size_t)(b * N2 + idx) * C1 + (j - 3)];
        }
        FT[j * 16 + k] = v;
    }
    __syncthreads();
    if (t >= C2) return;
    float acc[16];
#pragma unroll
    for (int k = 0; k < 16; k++) acc[k] = 0.0f;
    for (int j = 0; j < 131; j++) {
        float wj = w2[j * C2 + t];
        const float4* fp = (const float4*)(FT + j * 16);
#pragma unroll
        for (int q = 0; q < 4; q++) {
            float4 fv = fp[q];
            acc[q * 4 + 0] = fmaf(fv.x, wj, acc[q * 4 + 0]);
            acc[q * 4 + 1] = fmaf(fv.y, wj, acc[q * 4 + 1]);
            acc[q * 4 + 2] = fmaf(fv.z, wj, acc[q * 4 + 2]);
            acc[q * 4 + 3] = fmaf(fv.w, wj, acc[q * 4 + 3]);
        }
    }
    float bias = b2[t];
    double ds = 0.0, dq = 0.0;
    float* op = g_h2 + (size_t)bs * K2 * C2 + t;
#pragma unroll
    for (int k = 0; k < 16; k++) {
        float h = __fadd_rn(acc[k], bias);
        op[(size_t)k * C2] = h;
        ds += (double)h;
        dq += (double)h * (double)h;
    }
    atomicAdd(&g_sums[t], ds);
    atomicAdd(&g_sums[SMAX + t], dq);
}

// ---------------- level-2 normalize + relu + max over k -> l2_pts ----------------
__global__ void k_nm2(const float* __restrict__ g2, const float* __restrict__ be2,
                      float* __restrict__ out) {
    int bs = blockIdx.x, c = threadIdx.x;
    if (c >= C2) return;
    float mu = g_mu[c], rs = g_rs[c], ga = g2[c], be = be2[c];
    const float* hp = g_h2 + (size_t)bs * K2 * C2 + c;
    float m = __int_as_float(0xff800000);
#pragma unroll
    for (int k = 0; k < K2; k++) {
        float h = hp[(size_t)k * C2];
        float v = __fadd_rn(__fmul_rn(__fmul_rn(__fsub_rn(h, mu), rs), ga), be);
        m = fmaxf(m, fmaxf(v, 0.0f));
    }
    out[(size_t)bs * C2 + c] = m;
}

// ==================================================================================
extern "C" void kernel_launch(void* const* d_in, const int* in_sizes, int n_in,
                              void* d_out, int out_size) {
    const float* xyz = (const float*)d_in[0];
    const float* w1  = (const float*)d_in[1];
    const float* b1  = (const float*)d_in[2];
    const float* g1  = (const float*)d_in[3];
    const float* be1 = (const float*)d_in[4];
    const float* w2  = (const float*)d_in[5];
    const float* b2  = (const float*)d_in[6];
    const float* g2  = (const float*)d_in[7];
    const float* be2 = (const float*)d_in[8];
    float* out = (float*)d_out;
    float* l2xyz = out;                    // (4,256,3)
    float* l2pts = out + Bb * S2 * 3;      // (4,256,693)

    void *pP1, *pC1, *pC2, *pF1, *pF2, *pB1, *pB2;
    cudaGetSymbolAddress(&pP1, g_pack1);
    cudaGetSymbolAddress(&pC1, g_cent1);
    cudaGetSymbolAddress(&pC2, g_cent2);
    cudaGetSymbolAddress(&pF1, g_fps1);
    cudaGetSymbolAddress(&pF2, g_fps2);
    cudaGetSymbolAddress(&pB1, g_ball1);
    cudaGetSymbolAddress(&pB2, g_ball2);
    float4* P1 = (float4*)pP1;
    float4* Cn1 = (float4*)pC1;
    float4* Cn2 = (float4*)pC2;
    int* F1 = (int*)pF1;
    int* F2 = (int*)pF2;
    int* Ball1 = (int*)pB1;
    int* Ball2 = (int*)pB2;

    const float r2_1 = (float)(0.0025 * 0.0025);
    const float r2_2 = (float)(0.005 * 0.005);

    const int smem1 = 3 * N1 * (int)sizeof(float);   // 96 KB
    const int smem2 = 3 * N2 * (int)sizeof(float);   // 24 KB
    cudaFuncSetAttribute((const void*)k_fps<N1, S1, 1024, 8>,
                         cudaFuncAttributeMaxDynamicSharedMemorySize, smem1);
    cudaFuncSetAttribute((const void*)k_fps<N2, S2, 512, 4>,
                         cudaFuncAttributeMaxDynamicSharedMemorySize, smem2);

    // ---- level 1 ----
    k_pack1<<<(Bb * N1 + 255) / 256, 256>>>(xyz, P1);
    k_fps<N1, S1, 1024, 8><<<Bb, 1024, smem1>>>(P1, F1);
    k_gather<<<(Bb * S1 + 255) / 256, 256>>>(P1, F1, Cn1, S1, N1, nullptr);
    k_ball<N1, K1><<<(Bb * S1) / 8, 256>>>(P1, Cn1, S1, r2_1, Ball1);
    k_zero<<<2, 704>>>();
    k_mlp1<<<Bb * S1, C1>>>(xyz, w1, b1);
    k_stats<<<1, 704>>>(C1, (double)(Bb * S1 * K1));
    k_nm1<<<Bb * S1, C1>>>(xyz, w1, b1, g1, be1);

    // ---- level 2 ----
    k_fps<N2, S2, 512, 4><<<Bb, 512, smem2>>>(Cn1, F2);
    k_gather<<<(Bb * S2 + 255) / 256, 256>>>(Cn1, F2, Cn2, S2, N2, l2xyz);
    k_ball<N2, K2><<<(Bb * S2) / 8, 256>>>(Cn1, Cn2, S2, r2_2, Ball2);
    k_zero<<<2, 704>>>();
    k_mlp2<<<Bb * S2, 704>>>(w2, b2);
    k_stats<<<1, 704>>>(C2, (double)(Bb * S2 * K2));
    k_nm2<<<Bb * S2, 704>>>(g2, be2, l2pts);
}